// round 7
// baseline (speedup 1.0000x reference)
#include <cuda_runtime.h>
#include <mma.h>
#include <cuda_bf16.h>
#include <cstdint>
#include <math.h>

using namespace nvcuda;
typedef __nv_bfloat16 bf16;

// ---------------- problem dims ----------------
#define Bn 64
#define Nn 256
#define Fn 16
#define Hn 256
#define ROWS (Bn*Nn)          // 16384
#define N_ITERS 10
#define PLANE (ROWS*Hn)       // 4194304

// ---------------- scratch ----------------
__device__ float g_h  [PLANE];
__device__ float g_z  [PLANE];
__device__ float g_jcz[PLANE];
__device__ float g_jcr[PLANE];
__device__ float g_jch[PLANE];
__device__ float g_t2 [PLANE];
__device__ bf16 g_hP [2*PLANE];
__device__ bf16 g_tP [2*PLANE];
__device__ bf16 g_mP [2*PLANE];
__device__ bf16 g_rhP[2*PLANE];
__device__ bf16 g_daP[2*PLANE];
#define WOFF_MSG 0
#define WOFF_ZR  65536
#define WOFF_HB  327680
#define WOFF_R1  458752
#define WOFF_R2  524288
#define WTOTAL   589824
__device__ bf16 g_wH[WTOTAL];
__device__ bf16 g_wL[WTOTAL];

__device__ __forceinline__ float sigf(float x) { return 1.0f / (1.0f + expf(-x)); }

__device__ __forceinline__ uint32_t smem_u32(const void* p) {
    return (uint32_t)__cvta_generic_to_shared(p);
}
#define CP16(dst, src) asm volatile("cp.async.cg.shared.global [%0], [%1], 16;" :: "r"(dst), "l"(src))
#define CP_COMMIT()    asm volatile("cp.async.commit_group;" ::: "memory")
#define CP_WAIT(n)     asm volatile("cp.async.wait_group %0;" :: "n"(n) : "memory")

__device__ __forceinline__ void split1(float v, bf16& h, bf16& l) {
    h = __float2bfloat16(v);
    l = __float2bfloat16(v - __bfloat162float(h));
}
__device__ __forceinline__ void store_planes(bf16* Ph, bf16* Pl, size_t idx, float4 v) {
    __nv_bfloat162 h01 = __floats2bfloat162_rn(v.x, v.y);
    __nv_bfloat162 h23 = __floats2bfloat162_rn(v.z, v.w);
    float r0 = v.x - __low2float(h01), r1 = v.y - __high2float(h01);
    float r2 = v.z - __low2float(h23), r3 = v.w - __high2float(h23);
    __nv_bfloat162 l01 = __floats2bfloat162_rn(r0, r1);
    __nv_bfloat162 l23 = __floats2bfloat162_rn(r2, r3);
    uint2 hv, lv;
    hv.x = *(uint32_t*)&h01; hv.y = *(uint32_t*)&h23;
    lv.x = *(uint32_t*)&l01; lv.y = *(uint32_t*)&l23;
    *(uint2*)(Ph + idx) = hv;
    *(uint2*)(Pl + idx) = lv;
}

// ---------------- GEMM: cp.async pipeline + chain-broken 3-pass bf16 split ----------
enum { EPI_T = 0, EPI_M, EPI_ZR, EPI_GRU, EPI_R1, EPI_R2 };

#define STAGES 3
#define LDA 40
#define LDB 136
#define AHI_OFF 0
#define ALO_OFF 10240
#define BHI_OFF 20480
#define BLO_OFF 29184
#define STAGE_BYTES 37888
#define SMEM_BYTES (STAGES*STAGE_BYTES)   // 113664

template<int EPI>
__global__ void __launch_bounds__(256, 2)
tc_gemm(const bf16* __restrict__ A0h, const bf16* __restrict__ A0l,
        const bf16* __restrict__ A1h, const bf16* __restrict__ A1l,
        const bf16* __restrict__ Bh,  const bf16* __restrict__ Bl,
        int NB, int K, int batched,
        const float* __restrict__ bias,
        const float* __restrict__ jc,  const float* __restrict__ jc2,
        const float* __restrict__ Hb,  const float* __restrict__ Zb,
        float* Cf, bf16* Ch, bf16* Cl)
{
    extern __shared__ char sm[];
    const uint32_t smaddr = smem_u32(sm);

    const int tid = threadIdx.x, wid = tid >> 5;
    const int bn = blockIdx.x * 128, bm = blockIdx.y * 128;
    const int warp_m = wid >> 2;
    const int warp_n = wid & 3;

    int am = bm;
    size_t aoff = 0, boff = 0;
    if (batched) {
        const int b = bm >> 8;
        aoff = (size_t)b * (Nn * Hn);
        boff = (size_t)b * (Nn * Hn);
        am = bm & (Nn - 1);
    }

    const int NC = K >> 5;

    auto issue = [&](int kb) {
        const int buf = kb % STAGES;
        const uint32_t sb = smaddr + buf * STAGE_BYTES;
        const int kk = (kb & 7) * 32;
        const bf16 *ah, *al; int arow;
        if (kb < 8) { ah = A0h + aoff; al = A0l + aoff; arow = am; }
        else        { ah = A1h;        al = A1l;        arow = bm; }
        #pragma unroll
        for (int i = 0; i < 2; i++) {
            const int c = tid + i * 256;
            {
                const int r = c >> 2, c8 = (c & 3) * 8;
                const bf16* s1 = ah + (size_t)(arow + r) * Hn + kk + c8;
                const bf16* s2 = al + (size_t)(arow + r) * Hn + kk + c8;
                const uint32_t d = sb + AHI_OFF + (uint32_t)(r * LDA + c8) * 2;
                CP16(d, s1);
                CP16(d + (ALO_OFF - AHI_OFF), s2);
            }
            {
                const int r = c >> 4, c8 = (c & 15) * 8;
                const bf16* s1 = Bh + boff + (size_t)(kb * 32 + r) * NB + bn + c8;
                const bf16* s2 = Bl + boff + (size_t)(kb * 32 + r) * NB + bn + c8;
                const uint32_t d = sb + BHI_OFF + (uint32_t)(r * LDB + c8) * 2;
                CP16(d, s1);
                CP16(d + (BLO_OFF - BHI_OFF), s2);
            }
        }
    };

    wmma::fragment<wmma::accumulator, 16, 16, 16, float> acc[4][2];
    #pragma unroll
    for (int mi = 0; mi < 4; mi++)
        #pragma unroll
        for (int ni = 0; ni < 2; ni++)
            wmma::fill_fragment(acc[mi][ni], 0.0f);

    issue(0); CP_COMMIT();
    if (NC > 1) issue(1);
    CP_COMMIT();

    for (int kb = 0; kb < NC; kb++) {
        CP_WAIT(1);
        __syncthreads();

        if (kb + STAGES - 1 < NC) issue(kb + STAGES - 1);
        CP_COMMIT();

        const char* base = sm + (kb % STAGES) * STAGE_BYTES;
        const bf16* Ahi = (const bf16*)(base + AHI_OFF);
        const bf16* Alo = (const bf16*)(base + ALO_OFF);
        const bf16* Bhi = (const bf16*)(base + BHI_OFF);
        const bf16* Blo = (const bf16*)(base + BLO_OFF);

        #pragma unroll
        for (int kk = 0; kk < 2; kk++) {
            wmma::fragment<wmma::matrix_b, 16, 16, 16, bf16, wmma::row_major> bh[2], bl[2];
            #pragma unroll
            for (int ni = 0; ni < 2; ni++) {
                wmma::load_matrix_sync(bh[ni], Bhi + (kk * 16) * LDB + warp_n * 32 + ni * 16, LDB);
                wmma::load_matrix_sync(bl[ni], Blo + (kk * 16) * LDB + warp_n * 32 + ni * 16, LDB);
            }
            // ---- pass 1: A_hi x B_hi (sweep all 8 tiles; each acc touched once) ----
            #pragma unroll
            for (int mi = 0; mi < 4; mi++) {
                wmma::fragment<wmma::matrix_a, 16, 16, 16, bf16, wmma::row_major> a;
                wmma::load_matrix_sync(a, Ahi + (warp_m * 64 + mi * 16) * LDA + kk * 16, LDA);
                wmma::mma_sync(acc[mi][0], a, bh[0], acc[mi][0]);
                wmma::mma_sync(acc[mi][1], a, bh[1], acc[mi][1]);
            }
            // ---- pass 2: A_lo x B_hi ----
            #pragma unroll
            for (int mi = 0; mi < 4; mi++) {
                wmma::fragment<wmma::matrix_a, 16, 16, 16, bf16, wmma::row_major> a;
                wmma::load_matrix_sync(a, Alo + (warp_m * 64 + mi * 16) * LDA + kk * 16, LDA);
                wmma::mma_sync(acc[mi][0], a, bh[0], acc[mi][0]);
                wmma::mma_sync(acc[mi][1], a, bh[1], acc[mi][1]);
            }
            // ---- pass 3: A_hi x B_lo ----
            #pragma unroll
            for (int mi = 0; mi < 4; mi++) {
                wmma::fragment<wmma::matrix_a, 16, 16, 16, bf16, wmma::row_major> a;
                wmma::load_matrix_sync(a, Ahi + (warp_m * 64 + mi * 16) * LDA + kk * 16, LDA);
                wmma::mma_sync(acc[mi][0], a, bl[0], acc[mi][0]);
                wmma::mma_sync(acc[mi][1], a, bl[1], acc[mi][1]);
            }
        }
    }
    __syncthreads();

    // ---------------- epilogue via smem staging ----------------
    float* Cs = (float*)sm;
    #pragma unroll
    for (int mi = 0; mi < 4; mi++)
        #pragma unroll
        for (int ni = 0; ni < 2; ni++)
            wmma::store_matrix_sync(Cs + (warp_m * 64 + mi * 16) * 128 + warp_n * 32 + ni * 16,
                                    acc[mi][ni], 128, wmma::mem_row_major);
    __syncthreads();

    #pragma unroll
    for (int i = 0; i < 16; i++) {
        const int f = tid + i * 256;
        const int row = f >> 5, c4 = f & 31;
        const int grow = bm + row;
        const int gcol = bn + c4 * 4;
        float4 v = *(float4*)(Cs + row * 128 + c4 * 4);

        if (EPI == EPI_T || EPI == EPI_R1) {
            const size_t idx = (size_t)grow * Hn + gcol;
            float4 bv = *(const float4*)(bias + gcol);
            v.x += bv.x; v.y += bv.y; v.z += bv.z; v.w += bv.w;
            if (EPI == EPI_R1) { v.x=tanhf(v.x); v.y=tanhf(v.y); v.z=tanhf(v.z); v.w=tanhf(v.w); }
            store_planes(Ch, Cl, idx, v);
        } else if (EPI == EPI_M) {
            const size_t idx = (size_t)grow * Hn + gcol;
            v.x=tanhf(v.x); v.y=tanhf(v.y); v.z=tanhf(v.z); v.w=tanhf(v.w);
            store_planes(Ch, Cl, idx, v);
        } else if (EPI == EPI_ZR) {
            if (gcol < 256) {
                const size_t idx = (size_t)grow * Hn + gcol;
                float4 jv = *(const float4*)(jc + idx);
                v.x=sigf(v.x+jv.x); v.y=sigf(v.y+jv.y); v.z=sigf(v.z+jv.z); v.w=sigf(v.w+jv.w);
                *(float4*)(Cf + idx) = v;
            } else {
                const size_t idx = (size_t)grow * Hn + (gcol - 256);
                float4 jv = *(const float4*)(jc2 + idx);
                float4 hv = *(const float4*)(Hb + idx);
                v.x=sigf(v.x+jv.x)*hv.x; v.y=sigf(v.y+jv.y)*hv.y;
                v.z=sigf(v.z+jv.z)*hv.z; v.w=sigf(v.w+jv.w)*hv.w;
                store_planes(Ch, Cl, idx, v);
            }
        } else if (EPI == EPI_GRU) {
            const size_t idx = (size_t)grow * Hn + gcol;
            float4 jv = *(const float4*)(jc + idx);
            float4 hv = *(const float4*)(Hb + idx);
            float4 zv = *(const float4*)(Zb + idx);
            float t0=tanhf(v.x+jv.x), t1=tanhf(v.y+jv.y), t2=tanhf(v.z+jv.z), t3=tanhf(v.w+jv.w);
            v.x = hv.x + zv.x*(t0-hv.x); v.y = hv.y + zv.y*(t1-hv.y);
            v.z = hv.z + zv.z*(t2-hv.z); v.w = hv.w + zv.w*(t3-hv.w);
            *(float4*)(Cf + idx) = v;
            store_planes(Ch, Cl, idx, v);
        } else if (EPI == EPI_R2) {
            const size_t idx = (size_t)grow * Hn + gcol;
            float4 bv = *(const float4*)(bias + gcol);
            v.x += bv.x; v.y += bv.y; v.z += bv.z; v.w += bv.w;
            *(float4*)(Cf + idx) = v;
        }
    }
}

// ---------------- split / build kernels ----------------
__global__ void split_plain(const float* __restrict__ src, int n4, bf16* __restrict__ hi, bf16* __restrict__ lo)
{
    const int i = blockIdx.x * 256 + threadIdx.x;
    if (i < n4) {
        float4 v = *(const float4*)(src + i * 4);
        store_planes(hi, lo, (size_t)i * 4, v);
    }
}

__global__ void build_zrB(const float* __restrict__ Wz, const float* __restrict__ Wr,
                          const float* __restrict__ Uz, const float* __restrict__ Ur,
                          bf16* __restrict__ hi, bf16* __restrict__ lo)
{
    const int i = blockIdx.x * 256 + threadIdx.x;
    const int k = i >> 9, c = i & 511;
    float v;
    if (k < 256) v = (c < 256) ? Wz[k * Hn + c] : Wr[k * Hn + (c - 256)];
    else         v = (c < 256) ? Uz[(k - 256) * Hn + c] : Ur[(k - 256) * Hn + (c - 256)];
    bf16 h, l; split1(v, h, l);
    hi[i] = h; lo[i] = l;
}

__global__ void build_hB(const float* __restrict__ Wh, const float* __restrict__ Uh,
                         bf16* __restrict__ hi, bf16* __restrict__ lo)
{
    const int i = blockIdx.x * 256 + threadIdx.x;
    const int k = i >> 8, c = i & 255;
    float v = (k < 256) ? Wh[k * Hn + c] : Uh[(k - 256) * Hn + c];
    bf16 h, l; split1(v, h, l);
    hi[i] = h; lo[i] = l;
}

// ---------------- small kernels ----------------
__global__ void emb_kernel(const float* __restrict__ jets, const float* __restrict__ W_emb,
                           const float* __restrict__ b_emb, float* __restrict__ h,
                           bf16* __restrict__ hPh, bf16* __restrict__ hPl)
{
    const int row = blockIdx.x, j = threadIdx.x;
    __shared__ float sj[Fn];
    if (j < Fn) sj[j] = jets[(size_t)row * Fn + j];
    __syncthreads();
    float acc = b_emb[j];
    #pragma unroll
    for (int k = 0; k < Fn; k++) acc = fmaf(sj[k], W_emb[k * Hn + j], acc);
    const float v = tanhf(acc);
    const size_t idx = (size_t)row * Hn + j;
    h[idx] = v;
    bf16 hi, lo; split1(v, hi, lo);
    hPh[idx] = hi; hPl[idx] = lo;
}

__global__ void jc_kernel(const float* __restrict__ jets,
                          const float* __restrict__ Wz, const float* __restrict__ Wr,
                          const float* __restrict__ Wh,
                          const float* __restrict__ bz, const float* __restrict__ br,
                          const float* __restrict__ bh,
                          float* jcz, float* jcr, float* jch)
{
    const int row = blockIdx.x, j = threadIdx.x;
    __shared__ float sj[Fn];
    if (j < Fn) sj[j] = jets[(size_t)row * Fn + j];
    __syncthreads();
    float az = bz[j], ar = br[j], ah = bh[j];
    #pragma unroll
    for (int k = 0; k < Fn; k++) {
        const float s = sj[k];
        const int widx = (Hn + k) * Hn + j;
        az = fmaf(s, Wz[widx], az);
        ar = fmaf(s, Wr[widx], ar);
        ah = fmaf(s, Wh[widx], ah);
    }
    const size_t idx = (size_t)row * Hn + j;
    jcz[idx] = az; jcr[idx] = ar; jch[idx] = ah;
}

__global__ void reduce_kernel(const float* __restrict__ t2, float* __restrict__ out)
{
    const int idx = blockIdx.x * blockDim.x + threadIdx.x;
    const int b = idx >> 8, j = idx & 255;
    const float* p = t2 + (size_t)b * (Nn * Hn) + j;
    float acc = 0.0f;
    for (int n = 0; n < Nn; n++) acc += p[(size_t)n * Hn];
    out[idx] = acc;
}

// ---------------- launch ----------------
extern "C" void kernel_launch(void* const* d_in, const int* in_sizes, int n_in,
                              void* d_out, int out_size)
{
    const float* jets  = (const float*)d_in[0];
    const float* dads  = (const float*)d_in[1];
    const float* W_emb = (const float*)d_in[2];
    const float* b_emb = (const float*)d_in[3];
    const float* W_msg = (const float*)d_in[4];
    const float* b_msg = (const float*)d_in[5];
    const float* Wz    = (const float*)d_in[6];
    const float* Uz    = (const float*)d_in[7];
    const float* bz    = (const float*)d_in[8];
    const float* Wr    = (const float*)d_in[9];
    const float* Ur    = (const float*)d_in[10];
    const float* br    = (const float*)d_in[11];
    const float* Wh    = (const float*)d_in[12];
    const float* Uh    = (const float*)d_in[13];
    const float* bh    = (const float*)d_in[14];
    const float* W_r1  = (const float*)d_in[15];
    const float* b_r1  = (const float*)d_in[16];
    const float* W_r2  = (const float*)d_in[17];
    const float* b_r2  = (const float*)d_in[18];
    float* out = (float*)d_out;

    float *h, *z, *jcz, *jcr, *jch, *t2;
    bf16 *hP, *tP, *mP, *rhP, *daP, *wH, *wL;
    cudaGetSymbolAddress((void**)&h,   g_h);
    cudaGetSymbolAddress((void**)&z,   g_z);
    cudaGetSymbolAddress((void**)&jcz, g_jcz);
    cudaGetSymbolAddress((void**)&jcr, g_jcr);
    cudaGetSymbolAddress((void**)&jch, g_jch);
    cudaGetSymbolAddress((void**)&t2,  g_t2);
    cudaGetSymbolAddress((void**)&hP,  g_hP);
    cudaGetSymbolAddress((void**)&tP,  g_tP);
    cudaGetSymbolAddress((void**)&mP,  g_mP);
    cudaGetSymbolAddress((void**)&rhP, g_rhP);
    cudaGetSymbolAddress((void**)&daP, g_daP);
    cudaGetSymbolAddress((void**)&wH,  g_wH);
    cudaGetSymbolAddress((void**)&wL,  g_wL);

    bf16 *hPh = hP, *hPl = hP + PLANE;
    bf16 *tPh = tP, *tPl = tP + PLANE;
    bf16 *mPh = mP, *mPl = mP + PLANE;
    bf16 *rhPh = rhP, *rhPl = rhP + PLANE;
    bf16 *daPh = daP, *daPl = daP + PLANE;

    static bool attr_done = false;
    if (!attr_done) {
        cudaFuncSetAttribute(tc_gemm<EPI_T>,   cudaFuncAttributeMaxDynamicSharedMemorySize, SMEM_BYTES);
        cudaFuncSetAttribute(tc_gemm<EPI_M>,   cudaFuncAttributeMaxDynamicSharedMemorySize, SMEM_BYTES);
        cudaFuncSetAttribute(tc_gemm<EPI_ZR>,  cudaFuncAttributeMaxDynamicSharedMemorySize, SMEM_BYTES);
        cudaFuncSetAttribute(tc_gemm<EPI_GRU>, cudaFuncAttributeMaxDynamicSharedMemorySize, SMEM_BYTES);
        cudaFuncSetAttribute(tc_gemm<EPI_R1>,  cudaFuncAttributeMaxDynamicSharedMemorySize, SMEM_BYTES);
        cudaFuncSetAttribute(tc_gemm<EPI_R2>,  cudaFuncAttributeMaxDynamicSharedMemorySize, SMEM_BYTES);
        attr_done = true;
    }

    split_plain<<<PLANE/4/256, 256>>>(dads, PLANE/4, daPh, daPl);
    split_plain<<<65536/4/256, 256>>>(W_msg, 65536/4, wH + WOFF_MSG, wL + WOFF_MSG);
    split_plain<<<65536/4/256, 256>>>(W_r1,  65536/4, wH + WOFF_R1,  wL + WOFF_R1);
    split_plain<<<65536/4/256, 256>>>(W_r2,  65536/4, wH + WOFF_R2,  wL + WOFF_R2);
    build_zrB<<<262144/256, 256>>>(Wz, Wr, Uz, Ur, wH + WOFF_ZR, wL + WOFF_ZR);
    build_hB<<<131072/256, 256>>>(Wh, Uh, wH + WOFF_HB, wL + WOFF_HB);

    emb_kernel<<<ROWS, Hn>>>(jets, W_emb, b_emb, h, hPh, hPl);
    jc_kernel<<<ROWS, Hn>>>(jets, Wz, Wr, Wh, bz, br, bh, jcz, jcr, jch);

    dim3 grid2(2, ROWS/128);
    dim3 grid4(4, ROWS/128);
    for (int it = 0; it < N_ITERS; it++) {
        tc_gemm<EPI_T><<<grid2, 256, SMEM_BYTES>>>(
            hPh, hPl, nullptr, nullptr, wH + WOFF_MSG, wL + WOFF_MSG,
            256, 256, 0, b_msg, nullptr, nullptr, nullptr, nullptr,
            nullptr, tPh, tPl);
        tc_gemm<EPI_M><<<grid2, 256, SMEM_BYTES>>>(
            daPh, daPl, nullptr, nullptr, tPh, tPl,
            256, 256, 1, nullptr, nullptr, nullptr, nullptr, nullptr,
            nullptr, mPh, mPl);
        tc_gemm<EPI_ZR><<<grid4, 256, SMEM_BYTES>>>(
            mPh, mPl, hPh, hPl, wH + WOFF_ZR, wL + WOFF_ZR,
            512, 512, 0, nullptr, jcz, jcr, h, nullptr,
            z, rhPh, rhPl);
        tc_gemm<EPI_GRU><<<grid2, 256, SMEM_BYTES>>>(
            mPh, mPl, rhPh, rhPl, wH + WOFF_HB, wL + WOFF_HB,
            256, 512, 0, nullptr, jch, nullptr, h, z,
            h, hPh, hPl);
    }

    tc_gemm<EPI_R1><<<grid2, 256, SMEM_BYTES>>>(
        hPh, hPl, nullptr, nullptr, wH + WOFF_R1, wL + WOFF_R1,
        256, 256, 0, b_r1, nullptr, nullptr, nullptr, nullptr,
        nullptr, tPh, tPl);
    tc_gemm<EPI_R2><<<grid2, 256, SMEM_BYTES>>>(
        tPh, tPl, nullptr, nullptr, wH + WOFF_R2, wL + WOFF_R2,
        256, 256, 0, b_r2, nullptr, nullptr, nullptr, nullptr,
        t2, nullptr, nullptr);
    reduce_kernel<<<Bn, 256>>>(t2, out);
}